// round 3
// baseline (speedup 1.0000x reference)
#include <cuda_runtime.h>
#include <cstdint>

#define N_GRAPHS 1024
#define N_NODES  65536
#define N_EDGES  262144
#define D        256
#define D_IN     768
#define D_HID    512
#define D_OUT    256

// Scratch (no allocations allowed): collected [G, 3D] and hidden [G, D_HID]
__device__ float g_collected[N_GRAPHS * D_IN];
__device__ float g_hidden[N_GRAPHS * D_HID];

// ---------------------------------------------------------------------------
// Kernel 1: per-graph segment sums + concat, 1 CTA per graph, 256 threads.
// Ids are sorted, so each CTA binary-searches its [lo,hi) row range for both
// edges and nodes. Deterministic (no atomics), every output written once.
// ---------------------------------------------------------------------------
__global__ __launch_bounds__(256) void collect_kernel(
    const float* __restrict__ nodes,
    const float* __restrict__ edges,
    const float* __restrict__ globals_,
    const int* __restrict__ node_ids,
    const int* __restrict__ edge_ids,
    float* __restrict__ collected)
{
    const int g = blockIdx.x;
    const int t = threadIdx.x;   // 0..255 -> one feature column

    __shared__ int bounds[4];    // [e_lo, e_hi, n_lo, n_hi]
    if (t < 4) {
        const int* ids = (t < 2) ? edge_ids : node_ids;
        const int  n   = (t < 2) ? N_EDGES  : N_NODES;
        const int  target = g + (t & 1);   // lower_bound(g) / lower_bound(g+1)
        int lo = 0, hi = n;
        while (lo < hi) {
            int mid = (lo + hi) >> 1;
            if (ids[mid] < target) lo = mid + 1; else hi = mid;
        }
        bounds[t] = lo;
    }
    __syncthreads();

    // Edge aggregation -> cols [0, 256)
    {
        float acc = 0.f;
        const int lo = bounds[0], hi = bounds[1];
        int r = lo;
        // manual 4x unroll for MLP
        for (; r + 4 <= hi; r += 4) {
            float a0 = edges[(size_t)(r + 0) * D + t];
            float a1 = edges[(size_t)(r + 1) * D + t];
            float a2 = edges[(size_t)(r + 2) * D + t];
            float a3 = edges[(size_t)(r + 3) * D + t];
            acc += (a0 + a1) + (a2 + a3);
        }
        for (; r < hi; ++r) acc += edges[(size_t)r * D + t];
        collected[(size_t)g * D_IN + t] = acc;
    }

    // Node aggregation -> cols [256, 512)
    {
        float acc = 0.f;
        const int lo = bounds[2], hi = bounds[3];
        int r = lo;
        for (; r + 4 <= hi; r += 4) {
            float a0 = nodes[(size_t)(r + 0) * D + t];
            float a1 = nodes[(size_t)(r + 1) * D + t];
            float a2 = nodes[(size_t)(r + 2) * D + t];
            float a3 = nodes[(size_t)(r + 3) * D + t];
            acc += (a0 + a1) + (a2 + a3);
        }
        for (; r < hi; ++r) acc += nodes[(size_t)r * D + t];
        collected[(size_t)g * D_IN + D + t] = acc;
    }

    // Globals passthrough -> cols [512, 768)
    collected[(size_t)g * D_IN + 2 * D + t] = globals_[(size_t)g * D + t];
}

// ---------------------------------------------------------------------------
// Kernel 2: tiled SGEMM, C[M,N] = act(A[M,K] @ B[K,N] + bias)
// BM=64, BN=64, BK=32, 256 threads, 4x4 micro-tile per thread.
// ---------------------------------------------------------------------------
template <bool RELU>
__global__ __launch_bounds__(256) void sgemm_kernel(
    const float* __restrict__ A,
    const float* __restrict__ B,
    const float* __restrict__ bias,
    float* __restrict__ C,
    int M, int N, int K)
{
    constexpr int BM = 64, BN = 64, BK = 32;
    __shared__ float As[BK][BM];   // transposed: [k][m]
    __shared__ float Bs[BK][BN];   // [k][n]

    const int tid = threadIdx.x;
    const int tx = tid & 15;       // 0..15 -> n
    const int ty = tid >> 4;       // 0..15 -> m
    const int m0 = blockIdx.y * BM;
    const int n0 = blockIdx.x * BN;

    float acc[4][4] = {};

    for (int k0 = 0; k0 < K; k0 += BK) {
        // Load A tile 64x32: consecutive tid -> consecutive k (coalesced)
        #pragma unroll
        for (int i = 0; i < (BM * BK) / 256; ++i) {
            int idx = tid + i * 256;
            int k = idx & (BK - 1);
            int m = idx / BK;
            As[k][m] = A[(size_t)(m0 + m) * K + k0 + k];
        }
        // Load B tile 32x64: consecutive tid -> consecutive n (coalesced)
        #pragma unroll
        for (int i = 0; i < (BK * BN) / 256; ++i) {
            int idx = tid + i * 256;
            int n = idx & (BN - 1);
            int k = idx / BN;
            Bs[k][n] = B[(size_t)(k0 + k) * N + n0 + n];
        }
        __syncthreads();

        #pragma unroll
        for (int k = 0; k < BK; ++k) {
            float4 a = *reinterpret_cast<const float4*>(&As[k][ty * 4]);
            float4 b = *reinterpret_cast<const float4*>(&Bs[k][tx * 4]);
            float av[4] = {a.x, a.y, a.z, a.w};
            float bv[4] = {b.x, b.y, b.z, b.w};
            #pragma unroll
            for (int i = 0; i < 4; ++i)
                #pragma unroll
                for (int j = 0; j < 4; ++j)
                    acc[i][j] = fmaf(av[i], bv[j], acc[i][j]);
        }
        __syncthreads();
    }

    // Epilogue: bias (+ReLU), vectorized 16B stores
    #pragma unroll
    for (int i = 0; i < 4; ++i) {
        const int m = m0 + ty * 4 + i;
        const int n = n0 + tx * 4;
        float4 bv = *reinterpret_cast<const float4*>(&bias[n]);
        float4 v;
        v.x = acc[i][0] + bv.x;
        v.y = acc[i][1] + bv.y;
        v.z = acc[i][2] + bv.z;
        v.w = acc[i][3] + bv.w;
        if (RELU) {
            v.x = fmaxf(v.x, 0.f); v.y = fmaxf(v.y, 0.f);
            v.z = fmaxf(v.z, 0.f); v.w = fmaxf(v.w, 0.f);
        }
        *reinterpret_cast<float4*>(&C[(size_t)m * N + n]) = v;
    }
}

extern "C" void kernel_launch(void* const* d_in, const int* in_sizes, int n_in,
                              void* d_out, int out_size)
{
    const float* nodes    = (const float*)d_in[0];
    const float* edges    = (const float*)d_in[1];
    const float* globals_ = (const float*)d_in[2];
    const int*   node_ids = (const int*)d_in[3];
    const int*   edge_ids = (const int*)d_in[4];
    const float* W1       = (const float*)d_in[5];
    const float* b1       = (const float*)d_in[6];
    const float* W2       = (const float*)d_in[7];
    const float* b2       = (const float*)d_in[8];
    float* out = (float*)d_out;

    float* collected = nullptr;
    float* hidden = nullptr;
    cudaGetSymbolAddress((void**)&collected, g_collected);
    cudaGetSymbolAddress((void**)&hidden, g_hidden);

    // Phase 1: segment sums + concat
    collect_kernel<<<N_GRAPHS, 256>>>(nodes, edges, globals_, node_ids,
                                      edge_ids, collected);

    // Phase 2: hidden = relu(collected @ W1 + b1)   [1024,768]@[768,512]
    {
        dim3 grid(D_HID / 64, N_GRAPHS / 64);
        sgemm_kernel<true><<<grid, 256>>>(collected, W1, b1, hidden,
                                          N_GRAPHS, D_HID, D_IN);
    }
    // Phase 3: out = hidden @ W2 + b2               [1024,512]@[512,256]
    {
        dim3 grid(D_OUT / 64, N_GRAPHS / 64);
        sgemm_kernel<false><<<grid, 256>>>(hidden, W2, b2, out,
                                           N_GRAPHS, D_OUT, D_HID);
    }
}

// round 8
// speedup vs baseline: 1.8359x; 1.8359x over previous
#include <cuda_runtime.h>
#include <cstdint>

#define N_GRAPHS 1024
#define N_NODES  65536
#define N_EDGES  262144
#define D        256
#define D_IN     768
#define D_HID    512
#define D_OUT    256

// Scratch (no allocations allowed)
__device__ float g_collected[N_GRAPHS * D_IN];
__device__ float g_hidden[N_GRAPHS * D_HID];

// ---------------------------------------------------------------------------
// Kernel 1: segment sums + concat. 2 CTAs per graph (128 columns each),
// 256 threads: 32 float4 column-groups x 8 row-lanes. Sorted ids -> binary
// search for row ranges; no atomics, deterministic, float4 streaming loads.
// ---------------------------------------------------------------------------
__global__ __launch_bounds__(256) void collect_kernel(
    const float4* __restrict__ nodes,
    const float4* __restrict__ edges,
    const float4* __restrict__ globals_,
    const int* __restrict__ node_ids,
    const int* __restrict__ edge_ids,
    float* __restrict__ collected)
{
    const int g    = blockIdx.x >> 1;
    const int half = blockIdx.x & 1;      // which 128-column window
    const int t    = threadIdx.x;
    const int cg   = t & 31;              // col group (float4) 0..31
    const int rl   = t >> 5;              // row lane 0..7
    const int colf4 = half * 32 + cg;     // float4 index within row (D/4 = 64)

    __shared__ int bounds[4];             // [e_lo, e_hi, n_lo, n_hi]
    __shared__ float4 red[8][32];

    if (t < 4) {
        const int* ids = (t < 2) ? edge_ids : node_ids;
        const int  n   = (t < 2) ? N_EDGES  : N_NODES;
        const int  target = g + (t & 1);
        int lo = 0, hi = n;
        while (lo < hi) {
            int mid = (lo + hi) >> 1;
            if (ids[mid] < target) lo = mid + 1; else hi = mid;
        }
        bounds[t] = lo;
    }
    __syncthreads();

    // Edge accumulation
    float4 eacc = make_float4(0.f, 0.f, 0.f, 0.f);
    {
        const int lo = bounds[0], hi = bounds[1];
        #pragma unroll 4
        for (int r = lo + rl; r < hi; r += 8) {
            float4 v = __ldcs(&edges[(size_t)r * (D / 4) + colf4]);
            eacc.x += v.x; eacc.y += v.y; eacc.z += v.z; eacc.w += v.w;
        }
    }
    // Node accumulation
    float4 nacc = make_float4(0.f, 0.f, 0.f, 0.f);
    {
        const int lo = bounds[2], hi = bounds[3];
        #pragma unroll 4
        for (int r = lo + rl; r < hi; r += 8) {
            float4 v = __ldcs(&nodes[(size_t)r * (D / 4) + colf4]);
            nacc.x += v.x; nacc.y += v.y; nacc.z += v.z; nacc.w += v.w;
        }
    }

    // Globals passthrough (independent of smem reductions)
    if (rl == 1) {
        float4 gv = globals_[(size_t)g * (D / 4) + colf4];
        *reinterpret_cast<float4*>(&collected[(size_t)g * D_IN + 2 * D + colf4 * 4]) = gv;
    }

    // Reduce edge partials across row lanes
    red[rl][cg] = eacc;
    __syncthreads();
    if (rl == 0) {
        float4 s = red[0][cg];
        #pragma unroll
        for (int i = 1; i < 8; ++i) {
            float4 v = red[i][cg];
            s.x += v.x; s.y += v.y; s.z += v.z; s.w += v.w;
        }
        *reinterpret_cast<float4*>(&collected[(size_t)g * D_IN + colf4 * 4]) = s;
    }
    __syncthreads();

    // Reduce node partials
    red[rl][cg] = nacc;
    __syncthreads();
    if (rl == 0) {
        float4 s = red[0][cg];
        #pragma unroll
        for (int i = 1; i < 8; ++i) {
            float4 v = red[i][cg];
            s.x += v.x; s.y += v.y; s.z += v.z; s.w += v.w;
        }
        *reinterpret_cast<float4*>(&collected[(size_t)g * D_IN + D + colf4 * 4]) = s;
    }
}

// ---------------------------------------------------------------------------
// Kernel 2: TF32 tensor-core GEMM, C = act(A[M,K] @ B[K,N] + bias)
// CTA tile 64x64x32, 4 warps (2x2 of 32x32 warp tiles), mma.sync m16n8k8,
// fp32 accumulate, register-staged double buffering of the gmem->smem path.
// ---------------------------------------------------------------------------
__device__ __forceinline__ unsigned f2tf32(float x) {
    unsigned r;
    asm("cvt.rna.tf32.f32 %0, %1;" : "=r"(r) : "f"(x));
    return r;
}

__device__ __forceinline__ void mma_tf32(float (&c)[4],
                                         const unsigned (&a)[4],
                                         const unsigned (&b)[2]) {
    asm volatile(
        "mma.sync.aligned.m16n8k8.row.col.f32.tf32.tf32.f32 "
        "{%0,%1,%2,%3}, {%4,%5,%6,%7}, {%8,%9}, {%0,%1,%2,%3};\n"
        : "+f"(c[0]), "+f"(c[1]), "+f"(c[2]), "+f"(c[3])
        : "r"(a[0]), "r"(a[1]), "r"(a[2]), "r"(a[3]),
          "r"(b[0]), "r"(b[1]));
}

template <bool RELU>
__global__ __launch_bounds__(128) void mma_gemm(
    const float* __restrict__ A,
    const float* __restrict__ B,
    const float* __restrict__ bias,
    float* __restrict__ C,
    int M, int N, int K)
{
    constexpr int BM = 64, BN = 64, BK = 32;
    constexpr int APAD = 4, BPAD = 4;
    __shared__ unsigned As[BM][BK + APAD];  // tf32 bits, row-major [m][k]
    __shared__ unsigned Bs[BK][BN + BPAD];  // tf32 bits, [k][n]

    const int tid  = threadIdx.x;
    const int wid  = tid >> 5;
    const int lane = tid & 31;
    const int gid  = lane >> 2;   // 0..7
    const int tig  = lane & 3;    // 0..3
    const int m0 = blockIdx.y * BM;
    const int n0 = blockIdx.x * BN;
    const int wm = (wid & 1) * 32;   // warp m offset in tile
    const int wn = (wid >> 1) * 32;  // warp n offset in tile

    // gmem staging registers
    float4 sa[4], sb[4];
    float c[2][4][4];
    #pragma unroll
    for (int i = 0; i < 2; ++i)
        #pragma unroll
        for (int j = 0; j < 4; ++j)
            #pragma unroll
            for (int q = 0; q < 4; ++q) c[i][j][q] = 0.f;

    // A tile: 64 rows x 32 cols = 8 float4/row; tid -> (row=tid>>3, c4=tid&7), 4 passes
    // B tile: 32 rows x 64 cols = 16 float4/row; tid -> (row=tid>>4, c4=tid&15), 4 passes
    #define LOAD_TILES(k0)                                                        \
        {                                                                          \
            _Pragma("unroll")                                                      \
            for (int p = 0; p < 4; ++p) {                                          \
                int idx = tid + p * 128;                                           \
                int r = idx >> 3, c4 = idx & 7;                                    \
                sa[p] = *reinterpret_cast<const float4*>(                          \
                    &A[(size_t)(m0 + r) * K + (k0) + c4 * 4]);                     \
            }                                                                      \
            _Pragma("unroll")                                                      \
            for (int p = 0; p < 4; ++p) {                                          \
                int idx = tid + p * 128;                                           \
                int r = idx >> 4, c4 = idx & 15;                                   \
                sb[p] = *reinterpret_cast<const float4*>(                          \
                    &B[(size_t)((k0) + r) * N + n0 + c4 * 4]);                     \
            }                                                                      \
        }

    #define STORE_TILES()                                                         \
        {                                                                          \
            _Pragma("unroll")                                                      \
            for (int p = 0; p < 4; ++p) {                                          \
                int idx = tid + p * 128;                                           \
                int r = idx >> 3, c4 = idx & 7;                                    \
                uint4 u = make_uint4(f2tf32(sa[p].x), f2tf32(sa[p].y),             \
                                     f2tf32(sa[p].z), f2tf32(sa[p].w));            \
                *reinterpret_cast<uint4*>(&As[r][c4 * 4]) = u;                     \
            }                                                                      \
            _Pragma("unroll")                                                      \
            for (int p = 0; p < 4; ++p) {                                          \
                int idx = tid + p * 128;                                           \
                int r = idx >> 4, c4 = idx & 15;                                   \
                uint4 u = make_uint4(f2tf32(sb[p].x), f2tf32(sb[p].y),             \
                                     f2tf32(sb[p].z), f2tf32(sb[p].w));            \
                *reinterpret_cast<uint4*>(&Bs[r][c4 * 4]) = u;                     \
            }                                                                      \
        }

    LOAD_TILES(0);
    STORE_TILES();
    __syncthreads();

    for (int k0 = 0; k0 < K; k0 += BK) {
        const bool has_next = (k0 + BK) < K;
        if (has_next) LOAD_TILES(k0 + BK);   // LDG latency overlaps mma below

        #pragma unroll
        for (int ks = 0; ks < BK; ks += 8) {
            unsigned a[2][4], b[4][2];
            #pragma unroll
            for (int mt = 0; mt < 2; ++mt) {
                const int rb = wm + mt * 16 + gid;
                a[mt][0] = As[rb][ks + tig];
                a[mt][1] = As[rb + 8][ks + tig];
                a[mt][2] = As[rb][ks + tig + 4];
                a[mt][3] = As[rb + 8][ks + tig + 4];
            }
            #pragma unroll
            for (int nt = 0; nt < 4; ++nt) {
                const int cb = wn + nt * 8 + gid;
                b[nt][0] = Bs[ks + tig][cb];
                b[nt][1] = Bs[ks + tig + 4][cb];
            }
            #pragma unroll
            for (int mt = 0; mt < 2; ++mt)
                #pragma unroll
                for (int nt = 0; nt < 4; ++nt)
                    mma_tf32(c[mt][nt], a[mt], b[nt]);
        }
        __syncthreads();
        if (has_next) {
            STORE_TILES();
            __syncthreads();
        }
    }

    // Epilogue: bias (+ReLU). c0,c1 -> (row, col..col+1); c2,c3 -> (row+8, ...)
    #pragma unroll
    for (int mt = 0; mt < 2; ++mt) {
        const int row = m0 + wm + mt * 16 + gid;
        #pragma unroll
        for (int nt = 0; nt < 4; ++nt) {
            const int col = n0 + wn + nt * 8 + 2 * tig;
            float2 bv = *reinterpret_cast<const float2*>(&bias[col]);
            float2 v0, v1;
            v0.x = c[mt][nt][0] + bv.x;
            v0.y = c[mt][nt][1] + bv.y;
            v1.x = c[mt][nt][2] + bv.x;
            v1.y = c[mt][nt][3] + bv.y;
            if (RELU) {
                v0.x = fmaxf(v0.x, 0.f); v0.y = fmaxf(v0.y, 0.f);
                v1.x = fmaxf(v1.x, 0.f); v1.y = fmaxf(v1.y, 0.f);
            }
            *reinterpret_cast<float2*>(&C[(size_t)row * N + col]) = v0;
            *reinterpret_cast<float2*>(&C[(size_t)(row + 8) * N + col]) = v1;
        }
    }
    #undef LOAD_TILES
    #undef STORE_TILES
}

extern "C" void kernel_launch(void* const* d_in, const int* in_sizes, int n_in,
                              void* d_out, int out_size)
{
    const float* nodes    = (const float*)d_in[0];
    const float* edges    = (const float*)d_in[1];
    const float* globals_ = (const float*)d_in[2];
    const int*   node_ids = (const int*)d_in[3];
    const int*   edge_ids = (const int*)d_in[4];
    const float* W1       = (const float*)d_in[5];
    const float* b1       = (const float*)d_in[6];
    const float* W2       = (const float*)d_in[7];
    const float* b2       = (const float*)d_in[8];
    float* out = (float*)d_out;

    float* collected = nullptr;
    float* hidden = nullptr;
    cudaGetSymbolAddress((void**)&collected, g_collected);
    cudaGetSymbolAddress((void**)&hidden, g_hidden);

    // Phase 1: segment sums + concat (2 CTAs per graph)
    collect_kernel<<<2 * N_GRAPHS, 256>>>(
        (const float4*)nodes, (const float4*)edges, (const float4*)globals_,
        node_ids, edge_ids, collected);

    // Phase 2: hidden = relu(collected @ W1 + b1)   [1024,768]@[768,512]
    {
        dim3 grid(D_HID / 64, N_GRAPHS / 64);   // 8 x 16 = 128 CTAs
        mma_gemm<true><<<grid, 128>>>(collected, W1, b1, hidden,
                                      N_GRAPHS, D_HID, D_IN);
    }
    // Phase 3: out = hidden @ W2 + b2               [1024,512]@[512,256]
    {
        dim3 grid(D_OUT / 64, N_GRAPHS / 64);   // 4 x 16 = 64 CTAs
        mma_gemm<false><<<grid, 128>>>(hidden, W2, b2, out,
                                       N_GRAPHS, D_OUT, D_HID);
    }
}